// round 15
// baseline (speedup 1.0000x reference)
#include <cuda_runtime.h>
#include <cuda_bf16.h>
#include <cstdint>

#define NN 20000
#define NE 320000
#define NG 512
#define BN_CHUNKS 10

// ---------------- scratch (device globals; no allocation allowed) ----------
__device__ float g_bufA[NN * 1024];
__device__ float g_bufB[NN * 1024];
__device__ float g_deg[NN];
__device__ float g_dinv[NN];
__device__ float g_enorm[NE];
__device__ int   g_cnt[NN];
__device__ int   g_rowptr[NN + 1];
__device__ int   g_cursor[NN];
__device__ int   g_esrc[NE];
__device__ float g_ew[NE];
__device__ float g_aA[1024];
__device__ float g_aD[1024];
__device__ float g_ps[BN_CHUNKS * 1024];
__device__ float g_pq[BN_CHUNKS * 1024];
__device__ float g_gate[NN];
__device__ float g_gmax[NG];
__device__ float g_gsum[NG];
__device__ float g_pool[NG * 1024];
__device__ float g_p2[NG * 128];
__device__ float g_p3[NG * 16];

// ---------------- small utility kernels ------------------------------------
__global__ void k_fill(float* p, long n, float v) {
    long i = (long)blockIdx.x * blockDim.x + threadIdx.x;
    if (i < n) p[i] = v;
}
__global__ void k_filli(int* p, int n, int v) {
    int i = blockIdx.x * blockDim.x + threadIdx.x;
    if (i < n) p[i] = v;
}

__global__ void k_deg(const int* __restrict__ col, float* __restrict__ deg) {
    int e = blockIdx.x * blockDim.x + threadIdx.x;
    if (e < NE) atomicAdd(&deg[col[e]], 1.0f);
}

__global__ void k_dinv(const float* __restrict__ deg, float* __restrict__ dinv,
                       int* __restrict__ cnt) {
    int i = blockIdx.x * blockDim.x + threadIdx.x;
    if (i < NN) {
        dinv[i] = rsqrtf(deg[i]);
        cnt[i] = (int)(deg[i] - 0.5f);   // in-degree (deg includes self +1)
    }
}

__global__ void k_enorm(const int* __restrict__ row, const int* __restrict__ col,
                        const float* __restrict__ dinv, float* __restrict__ nrm) {
    int e = blockIdx.x * blockDim.x + threadIdx.x;
    if (e < NE) nrm[e] = dinv[row[e]] * dinv[col[e]];
}

// single-block exclusive scan of cnt -> rowptr (chunked Hillis-Steele)
__global__ void k_scan(const int* __restrict__ cnt, int* __restrict__ rowptr) {
    __shared__ int s[1024];
    const int CH = 20;
    int t = threadIdx.x;
    int base = t * CH;
    int sum = 0;
    for (int i = 0; i < CH; i++) {
        int idx = base + i;
        if (idx < NN) sum += cnt[idx];
    }
    s[t] = sum;
    __syncthreads();
    for (int off = 1; off < 1024; off <<= 1) {
        int v = (t >= off) ? s[t - off] : 0;
        __syncthreads();
        s[t] += v;
        __syncthreads();
    }
    int excl = (t == 0) ? 0 : s[t - 1];
    int run = excl;
    for (int i = 0; i < CH; i++) {
        int idx = base + i;
        if (idx < NN) { rowptr[idx] = run; run += cnt[idx]; }
    }
    if (t == 1023) rowptr[NN] = s[1023];
}

__global__ void k_scatter(const int* __restrict__ row, const int* __restrict__ col,
                          const float* __restrict__ nrm, const int* __restrict__ rowptr,
                          int* __restrict__ cursor, int* __restrict__ esrc,
                          float* __restrict__ ew) {
    int e = blockIdx.x * blockDim.x + threadIdx.x;
    if (e >= NE) return;
    int c = col[e];
    int p = atomicAdd(&cursor[c], 1);
    int o = rowptr[c] + p;
    esrc[o] = row[e];
    ew[o] = nrm[e];
}

// ---------------- CSR gather aggregation ------------------------------------
// dst[v] = dinv[v]^2 * f(src[v]) + sum_{edges u->v} w_e * f(src[u])
// f = pending BN affine (AFF=1) or identity. Warp per dst node; lane l owns
// float4 chunks at l*4 + c*128. Edge list walked once; zero atomics.
template <int NCH, int AFF>   // F = NCH * 128
__global__ __launch_bounds__(256) void k_agg_gather(
    const float* __restrict__ src, float* __restrict__ dst,
    const int* __restrict__ rowptr, const int* __restrict__ esrc,
    const float* __restrict__ ew, const float* __restrict__ dinv,
    const float* __restrict__ inA, const float* __restrict__ inD)
{
    int gw = (blockIdx.x * blockDim.x + threadIdx.x) >> 5;
    if (gw >= NN) return;
    int lane = threadIdx.x & 31;
    const int F = NCH * 128;

    float4 a4[NCH], d4[NCH];
    if (AFF) {
#pragma unroll
        for (int c = 0; c < NCH; c++) {
            a4[c] = *(const float4*)(inA + lane * 4 + c * 128);
            d4[c] = *(const float4*)(inD + lane * 4 + c * 128);
        }
    }

    float4 acc[NCH];
    float dv = dinv[gw];
    float w0 = dv * dv;
    const float* srow = src + (long)gw * F + lane * 4;
#pragma unroll
    for (int c = 0; c < NCH; c++) {
        float4 t = *(const float4*)(srow + c * 128);
        if (AFF) {
            t.x = fmaf(a4[c].x, t.x, d4[c].x); t.y = fmaf(a4[c].y, t.y, d4[c].y);
            t.z = fmaf(a4[c].z, t.z, d4[c].z); t.w = fmaf(a4[c].w, t.w, d4[c].w);
        }
        acc[c] = make_float4(w0 * t.x, w0 * t.y, w0 * t.z, w0 * t.w);
    }

    int k0 = rowptr[gw], k1 = rowptr[gw + 1];
    for (int kb = k0; kb < k1; kb += 32) {
        int kk = kb + lane;
        int u_r = (kk < k1) ? esrc[kk] : 0;
        float w_r = (kk < k1) ? ew[kk] : 0.0f;
        int cnt = min(32, k1 - kb);
        for (int j = 0; j < cnt; j++) {
            int u = __shfl_sync(0xffffffffu, u_r, j);
            float w = __shfl_sync(0xffffffffu, w_r, j);
            const float* r = src + (long)u * F + lane * 4;
#pragma unroll
            for (int c = 0; c < NCH; c++) {
                float4 t = *(const float4*)(r + c * 128);
                if (AFF) {
                    t.x = fmaf(a4[c].x, t.x, d4[c].x); t.y = fmaf(a4[c].y, t.y, d4[c].y);
                    t.z = fmaf(a4[c].z, t.z, d4[c].z); t.w = fmaf(a4[c].w, t.w, d4[c].w);
                }
                acc[c].x += w * t.x; acc[c].y += w * t.y;
                acc[c].z += w * t.z; acc[c].w += w * t.w;
            }
        }
    }

    float* drow = dst + (long)gw * F + lane * 4;
#pragma unroll
    for (int c = 0; c < NCH; c++)
        *(float4*)(drow + c * 128) = acc[c];
}

// small-F (F <= 32) gather: lane per feature (layer 1 only, no affine)
__global__ __launch_bounds__(256) void k_agg_gather_s(
    const float* __restrict__ src, float* __restrict__ dst,
    const int* __restrict__ rowptr, const int* __restrict__ esrc,
    const float* __restrict__ ew, const float* __restrict__ dinv, int F)
{
    int gw = (blockIdx.x * blockDim.x + threadIdx.x) >> 5;
    if (gw >= NN) return;
    int lane = threadIdx.x & 31;
    float acc = 0.0f;
    float dv = dinv[gw];
    float w0 = dv * dv;
    if (lane < F) acc = w0 * src[(long)gw * F + lane];
    int k0 = rowptr[gw], k1 = rowptr[gw + 1];
    for (int kb = k0; kb < k1; kb += 32) {
        int kk = kb + lane;
        int u_r = (kk < k1) ? esrc[kk] : 0;
        float w_r = (kk < k1) ? ew[kk] : 0.0f;
        int cnt = min(32, k1 - kb);
        for (int j = 0; j < cnt; j++) {
            int u = __shfl_sync(0xffffffffu, u_r, j);
            float w = __shfl_sync(0xffffffffu, w_r, j);
            if (lane < F) acc += w * src[(long)u * F + lane];
        }
    }
    if (lane < F) dst[(long)gw * F + lane] = acc;
}

// ---------------- vectorized global reduction helper ------------------------
__device__ __forceinline__ void red_add_v4(float* p, float a, float b, float c, float d) {
    asm volatile("red.global.add.v4.f32 [%0], {%1, %2, %3, %4};"
                 :: "l"(p), "f"(a), "f"(b), "f"(c), "f"(d) : "memory");
}

// ---------------- 3x-BF16 tensor-core GEMM ---------------------------------
// C[M,N] = f(A)[M,K] @ W[K,N] (+bias, relu); f = pending BN affine on A's
// columns (or identity). Block 128x128, 8 warps of 64x32, mma m16n8k16 bf16
// hi/lo compensated; BK=32 double-buffered; splits done once at stage time.
__device__ __forceinline__ uint2 bf16split2(float f0, float f1) {
    __nv_bfloat162 h = __floats2bfloat162_rn(f0, f1);     // .x = f0 (low k)
    float h0 = __bfloat162float(__low2bfloat16(h));
    float h1 = __bfloat162float(__high2bfloat16(h));
    __nv_bfloat162 l = __floats2bfloat162_rn(f0 - h0, f1 - h1);
    uint2 r;
    r.x = *reinterpret_cast<uint32_t*>(&h);
    r.y = *reinterpret_cast<uint32_t*>(&l);
    return r;
}

__device__ __forceinline__ void mma_bf16(float* d, const uint32_t* a, const uint32_t* b) {
    asm volatile(
        "mma.sync.aligned.m16n8k16.row.col.f32.bf16.bf16.f32 "
        "{%0,%1,%2,%3}, {%4,%5,%6,%7}, {%8,%9}, {%0,%1,%2,%3};"
        : "+f"(d[0]), "+f"(d[1]), "+f"(d[2]), "+f"(d[3])
        : "r"(a[0]), "r"(a[1]), "r"(a[2]), "r"(a[3]), "r"(b[0]), "r"(b[1]));
}

#define KP 16      // k-pairs per BK=32 tile
#define LDP 132    // padded row length (uint2 elements)

__global__ __launch_bounds__(256) void k_gemm_bf16x3(
    const float* __restrict__ A, const float* __restrict__ W,
    const float* __restrict__ bias, float* __restrict__ C,
    const float* __restrict__ inA, const float* __restrict__ inD,
    int M, int N, int K, int doRelu)
{
    extern __shared__ uint2 smem[];
    uint2* Asm = smem;                    // [2][KP][LDP]  (hi,lo) of A k-pairs
    uint2* Bsm = smem + 2 * KP * LDP;     // [2][KP][LDP]  (hi,lo) of W k-pairs
#define AS(b, kp, m) Asm[((b) * KP + (kp)) * LDP + (m)]
#define BS(b, kp, n) Bsm[((b) * KP + (kp)) * LDP + (n)]

    const int tid = threadIdx.x;
    const int lane = tid & 31;
    const int warp = tid >> 5;
    const int wm = warp >> 2, wn = warp & 3;
    const int gr = lane >> 2, gk = lane & 3;
    const int bm = blockIdx.y * 128, bn = blockIdx.x * 128;

    float acc[4][4][4];
#pragma unroll
    for (int i = 0; i < 4; i++)
#pragma unroll
        for (int j = 0; j < 4; j++)
#pragma unroll
            for (int r = 0; r < 4; r++) acc[i][j][r] = 0.0f;

    const int nc = (K + 31) / 32;
    const bool vec = (K & 31) == 0;

    const int ar = tid >> 1, akb = (tid & 1) * 16;  // A: row, k base (16 wide)
    const int wr2 = tid >> 5, wc = (tid & 31) * 4;  // B: k-pair row, col base

    float ra[16];
    float rb[16];

    auto fetch = [&](int c) {
        int k0 = c * 32;
        int g = bm + ar;
        if (vec) {
            if (g < M) {
                const float* p = A + (long)g * K + k0 + akb;
#pragma unroll
                for (int h = 0; h < 4; h++) {
                    float4 v = *(const float4*)(p + h * 4);
                    ra[h * 4 + 0] = v.x; ra[h * 4 + 1] = v.y;
                    ra[h * 4 + 2] = v.z; ra[h * 4 + 3] = v.w;
                }
            } else {
#pragma unroll
                for (int q = 0; q < 16; q++) ra[q] = 0.0f;
            }
            if (inA) {
#pragma unroll
                for (int h = 0; h < 4; h++) {
                    float4 av = *(const float4*)(inA + k0 + akb + h * 4);
                    float4 dv = *(const float4*)(inD + k0 + akb + h * 4);
                    ra[h * 4 + 0] = fmaf(av.x, ra[h * 4 + 0], dv.x);
                    ra[h * 4 + 1] = fmaf(av.y, ra[h * 4 + 1], dv.y);
                    ra[h * 4 + 2] = fmaf(av.z, ra[h * 4 + 2], dv.z);
                    ra[h * 4 + 3] = fmaf(av.w, ra[h * 4 + 3], dv.w);
                }
            }
        } else {
#pragma unroll
            for (int q = 0; q < 16; q++) {
                int kk = k0 + akb + q;
                float v = (g < M && kk < K) ? A[(long)g * K + kk] : 0.0f;
                if (inA && kk < K) v = fmaf(inA[kk], v, inD[kk]);
                ra[q] = v;
            }
        }
        // B rows: k-pair wr2 -> rows k0+2*wr2, +1 ; k-pair wr2+8 -> +16, +17
        int r0 = k0 + 2 * wr2;
#pragma unroll
        for (int h = 0; h < 4; h++) {
            int kk = r0 + (h >> 1) * 16 + (h & 1);
            if (kk < K) {
                float4 v = *(const float4*)(W + (long)kk * N + bn + wc);
                rb[h * 4 + 0] = v.x; rb[h * 4 + 1] = v.y;
                rb[h * 4 + 2] = v.z; rb[h * 4 + 3] = v.w;
            } else {
                rb[h * 4 + 0] = rb[h * 4 + 1] = rb[h * 4 + 2] = rb[h * 4 + 3] = 0.0f;
            }
        }
    };
    auto stage = [&](int buf) {
#pragma unroll
        for (int q = 0; q < 8; q++)
            AS(buf, (tid & 1) * 8 + q, ar) = bf16split2(ra[2 * q], ra[2 * q + 1]);
#pragma unroll
        for (int c4 = 0; c4 < 4; c4++) {
            BS(buf, wr2, wc + c4)     = bf16split2(rb[c4],     rb[4 + c4]);
            BS(buf, wr2 + 8, wc + c4) = bf16split2(rb[8 + c4], rb[12 + c4]);
        }
    };

    fetch(0);
    stage(0);
    __syncthreads();

    for (int c = 0; c < nc; c++) {
        int buf = c & 1;
        if (c + 1 < nc) fetch(c + 1);   // LDGs overlap compute below
#pragma unroll
        for (int kk = 0; kk < 2; kk++) {
            int kb = kk * 8;
            uint32_t ah[4][4], al[4][4], bh[4][2], bl[4][2];
#pragma unroll
            for (int i = 0; i < 4; i++) {
                int m = wm * 64 + i * 16 + gr;
                uint2 v0 = AS(buf, kb + gk, m);
                uint2 v1 = AS(buf, kb + gk, m + 8);
                uint2 v2 = AS(buf, kb + gk + 4, m);
                uint2 v3 = AS(buf, kb + gk + 4, m + 8);
                ah[i][0] = v0.x; al[i][0] = v0.y;
                ah[i][1] = v1.x; al[i][1] = v1.y;
                ah[i][2] = v2.x; al[i][2] = v2.y;
                ah[i][3] = v3.x; al[i][3] = v3.y;
            }
#pragma unroll
            for (int j = 0; j < 4; j++) {
                int n = wn * 32 + j * 8 + gr;
                uint2 u0 = BS(buf, kb + gk, n);
                uint2 u1 = BS(buf, kb + gk + 4, n);
                bh[j][0] = u0.x; bl[j][0] = u0.y;
                bh[j][1] = u1.x; bl[j][1] = u1.y;
            }
#pragma unroll
            for (int i = 0; i < 4; i++)
#pragma unroll
                for (int j = 0; j < 4; j++) {
                    mma_bf16(acc[i][j], al[i], bh[j]);   // lo*hi
                    mma_bf16(acc[i][j], ah[i], bl[j]);   // hi*lo
                    mma_bf16(acc[i][j], ah[i], bh[j]);   // hi*hi
                }
        }
        if (c + 1 < nc) {
            stage((c + 1) & 1);   // writes buf^1: protected by previous sync
        }
        __syncthreads();
    }

    // epilogue
#pragma unroll
    for (int i = 0; i < 4; i++) {
        int r0 = bm + wm * 64 + i * 16 + gr;
        int r1 = r0 + 8;
#pragma unroll
        for (int j = 0; j < 4; j++) {
            int cc = bn + wn * 32 + j * 8 + gk * 2;
            float b0 = bias ? bias[cc] : 0.0f;
            float b1 = bias ? bias[cc + 1] : 0.0f;
            float v0 = acc[i][j][0] + b0, v1 = acc[i][j][1] + b1;
            float v2 = acc[i][j][2] + b0, v3 = acc[i][j][3] + b1;
            if (doRelu) {
                v0 = fmaxf(v0, 0.0f); v1 = fmaxf(v1, 0.0f);
                v2 = fmaxf(v2, 0.0f); v3 = fmaxf(v3, 0.0f);
            }
            if (r0 < M) *(float2*)(C + (long)r0 * N + cc) = make_float2(v0, v1);
            if (r1 < M) *(float2*)(C + (long)r1 * N + cc) = make_float2(v2, v3);
        }
    }
#undef AS
#undef BS
}

#define GEMM_SMEM (2 * 2 * KP * LDP * (int)sizeof(uint2))

// ---------------- BatchNorm stats (+ optional bias/relu write-back) --------
__global__ void k_bnpart(float* __restrict__ X, const float* __restrict__ bias,
                         int writeback, int M, int N,
                         float* __restrict__ ps, float* __restrict__ pq) {
    int lane = threadIdx.x & 31, ry = threadIdx.x >> 5;  // block 256 = 8x32
    int c = blockIdx.x * 32 + lane;
    int nch = gridDim.y;
    int per = (M + nch - 1) / nch;
    int r0 = blockIdx.y * per;
    int r1 = min(M, r0 + per);
    float s = 0.0f, q = 0.0f;
    if (c < N) {
        float bb = bias ? bias[c] : 0.0f;
        bool rl = (bias != nullptr);
        for (int r = r0 + ry; r < r1; r += 8) {
            float v = X[(long)r * N + c];
            if (rl) v = fmaxf(v + bb, 0.0f);
            if (writeback) X[(long)r * N + c] = v;
            s += v;
            q += v * v;
        }
    }
    __shared__ float sh[16][32];
    sh[ry][lane] = s;
    sh[8 + ry][lane] = q;
    __syncthreads();
    if (ry == 0 && c < N) {
#pragma unroll
        for (int i = 1; i < 8; i++) { s += sh[i][lane]; q += sh[8 + i][lane]; }
        ps[blockIdx.y * N + c] = s;
        pq[blockIdx.y * N + c] = q;
    }
}

// stats -> per-feature affine (a = gamma*rstd, d = beta - a*mean)
__global__ void k_bnfin(const float* __restrict__ ps, const float* __restrict__ pq,
                        const float* __restrict__ gm, const float* __restrict__ bt,
                        float* __restrict__ aA, float* __restrict__ aD,
                        int N, int nch) {
    int c = blockIdx.x * blockDim.x + threadIdx.x;
    if (c >= N) return;
    float s = 0.0f, q = 0.0f;
    for (int i = 0; i < nch; i++) { s += ps[i * N + c]; q += pq[i * N + c]; }
    float m = s / (float)NN;
    float var = q / (float)NN - m * m;
    float r = rsqrtf(fmaxf(var, 0.0f) + 1e-5f);
    float a = gm[c] * r;
    aA[c] = a;
    aD[c] = bt[c] - a * m;
}

// ---------------- global attention pooling (pending affine applied) --------
__global__ void k_gate(const float* __restrict__ H, const float* __restrict__ Wg,
                       const float* __restrict__ bg, const float* __restrict__ aA,
                       const float* __restrict__ aD, float* __restrict__ gate) {
    int t = blockIdx.x * blockDim.x + threadIdx.x;
    int v = t >> 5, lane = t & 31;
    if (v >= NN) return;
    const float* h = H + (long)v * 1024;
    float s = 0.0f;
    for (int k = lane; k < 1024; k += 32)
        s += fmaf(aA[k], h[k], aD[k]) * Wg[k];
#pragma unroll
    for (int o = 16; o; o >>= 1) s += __shfl_down_sync(0xffffffffu, s, o);
    if (lane == 0) gate[v] = s + bg[0];
}

__global__ void k_segmax(const float* __restrict__ gate, const int* __restrict__ batch,
                         float* __restrict__ gmax) {
    int i = blockIdx.x * blockDim.x + threadIdx.x;
    if (i >= NN) return;
    float v = gate[i];
    float* addr = &gmax[batch[i]];
    int old = __float_as_int(*addr);
    while (v > __int_as_float(old)) {
        int prev = atomicCAS((int*)addr, old, __float_as_int(v));
        if (prev == old) break;
        old = prev;
    }
}

__global__ void k_exps(float* __restrict__ gate, const int* __restrict__ batch,
                       const float* __restrict__ gmax, float* __restrict__ gsum) {
    int i = blockIdx.x * blockDim.x + threadIdx.x;
    if (i >= NN) return;
    int b = batch[i];
    float e = expf(gate[i] - gmax[b]);
    gate[i] = e;
    atomicAdd(&gsum[b], e);
}

__global__ void k_coef(float* __restrict__ gate, const int* __restrict__ batch,
                       const float* __restrict__ gsum) {
    int i = blockIdx.x * blockDim.x + threadIdx.x;
    if (i >= NN) return;
    gate[i] = gate[i] / gsum[batch[i]];
}

// float4 + red.v4 pooling (affine applied on the fly)
__global__ void k_pool4(const float* __restrict__ H, const float* __restrict__ gate,
                        const int* __restrict__ batch, const float* __restrict__ aA,
                        const float* __restrict__ aD, float* __restrict__ pool) {
    long i = (long)blockIdx.x * blockDim.x + threadIdx.x;
    if (i >= (long)NN * 256) return;
    int v = (int)(i >> 8);
    int f = (int)(i & 255) * 4;
    float wgt = gate[v];
    float4 h = *(const float4*)(H + ((long)v << 10) + f);
    float4 a = *(const float4*)(aA + f);
    float4 d = *(const float4*)(aD + f);
    h.x = fmaf(a.x, h.x, d.x); h.y = fmaf(a.y, h.y, d.y);
    h.z = fmaf(a.z, h.z, d.z); h.w = fmaf(a.w, h.w, d.w);
    float* p = pool + ((long)batch[v] << 10) + f;
    red_add_v4(p, wgt * h.x, wgt * h.y, wgt * h.z, wgt * h.w);
}

// ---------------- small MLP GEMMs ------------------------------------------
__global__ void k_mlp(const float* __restrict__ X, const float* __restrict__ W,
                      const float* __restrict__ bias, float* __restrict__ Y,
                      int M, int N, int K, int relu) {
    int i = blockIdx.x * blockDim.x + threadIdx.x;
    if (i >= M * N) return;
    int m = i / N, n = i % N;
    float s = bias[n];
    for (int k = 0; k < K; k++) s += X[m * K + k] * W[k * N + n];
    if (relu) s = fmaxf(s, 0.0f);
    Y[i] = s;
}

// ---------------- launch -----------------------------------------------------
extern "C" void kernel_launch(void* const* d_in, const int* in_sizes, int n_in,
                              void* d_out, int out_size) {
    (void)in_sizes; (void)n_in; (void)out_size;
    const float* x = (const float*)d_in[0];
    const int* ei = (const int*)d_in[1];
    const int* row = ei;
    const int* col = ei + NE;
    const int* batch = (const int*)d_in[2];
    const float *W[5], *b[5], *g[5], *be[5];
    for (int i = 0; i < 5; i++) {
        W[i]  = (const float*)d_in[3 + 4 * i];
        b[i]  = (const float*)d_in[4 + 4 * i];
        g[i]  = (const float*)d_in[5 + 4 * i];
        be[i] = (const float*)d_in[6 + 4 * i];
    }
    const float* Wg  = (const float*)d_in[23];
    const float* bg  = (const float*)d_in[24];
    const float* Wf2 = (const float*)d_in[25];
    const float* bf2 = (const float*)d_in[26];
    const float* Wf3 = (const float*)d_in[27];
    const float* bf3 = (const float*)d_in[28];
    const float* Wf4 = (const float*)d_in[29];
    const float* bf4 = (const float*)d_in[30];

    static int s_attr_done = 0;
    if (!s_attr_done) {
        cudaFuncSetAttribute(k_gemm_bf16x3,
                             cudaFuncAttributeMaxDynamicSharedMemorySize, GEMM_SMEM);
        s_attr_done = 1;
    }

    float *A, *B, *deg, *dinv, *nrm, *ps, *pq, *ew, *aA, *aD;
    float *gate, *gmax, *gsum, *pool, *p2, *p3;
    int *cnt, *rowptr, *cursor, *esrc;
    cudaGetSymbolAddress((void**)&A, g_bufA);
    cudaGetSymbolAddress((void**)&B, g_bufB);
    cudaGetSymbolAddress((void**)&deg, g_deg);
    cudaGetSymbolAddress((void**)&dinv, g_dinv);
    cudaGetSymbolAddress((void**)&nrm, g_enorm);
    cudaGetSymbolAddress((void**)&cnt, g_cnt);
    cudaGetSymbolAddress((void**)&rowptr, g_rowptr);
    cudaGetSymbolAddress((void**)&cursor, g_cursor);
    cudaGetSymbolAddress((void**)&esrc, g_esrc);
    cudaGetSymbolAddress((void**)&ew, g_ew);
    cudaGetSymbolAddress((void**)&aA, g_aA);
    cudaGetSymbolAddress((void**)&aD, g_aD);
    cudaGetSymbolAddress((void**)&ps, g_ps);
    cudaGetSymbolAddress((void**)&pq, g_pq);
    cudaGetSymbolAddress((void**)&gate, g_gate);
    cudaGetSymbolAddress((void**)&gmax, g_gmax);
    cudaGetSymbolAddress((void**)&gsum, g_gsum);
    cudaGetSymbolAddress((void**)&pool, g_pool);
    cudaGetSymbolAddress((void**)&p2, g_p2);
    cudaGetSymbolAddress((void**)&p3, g_p3);

    // ---- graph normalization + CSR build (depends only on edge_index) ----
    k_fill<<<(NN + 255) / 256, 256>>>(deg, NN, 1.0f);            // self-loop
    k_deg<<<(NE + 255) / 256, 256>>>(col, deg);
    k_dinv<<<(NN + 255) / 256, 256>>>(deg, dinv, cnt);
    k_enorm<<<(NE + 255) / 256, 256>>>(row, col, dinv, nrm);
    k_scan<<<1, 1024>>>(cnt, rowptr);
    k_filli<<<(NN + 255) / 256, 256>>>(cursor, NN, 0);
    k_scatter<<<(NE + 255) / 256, 256>>>(row, col, nrm, rowptr, cursor, esrc, ew);

    const int AGG_GRID = (NN * 32 + 255) / 256;
    auto agg = [&](const float* src, float* dst, int F, bool aff) {
        if (F == 512) {
            if (aff) k_agg_gather<4, 1><<<AGG_GRID, 256>>>(src, dst, rowptr, esrc, ew, dinv, aA, aD);
            else     k_agg_gather<4, 0><<<AGG_GRID, 256>>>(src, dst, rowptr, esrc, ew, dinv, nullptr, nullptr);
        } else if (F == 256) {
            if (aff) k_agg_gather<2, 1><<<AGG_GRID, 256>>>(src, dst, rowptr, esrc, ew, dinv, aA, aD);
            else     k_agg_gather<2, 0><<<AGG_GRID, 256>>>(src, dst, rowptr, esrc, ew, dinv, nullptr, nullptr);
        } else {
            k_agg_gather_s<<<AGG_GRID, 256>>>(src, dst, rowptr, esrc, ew, dinv, F);
        }
    };
    auto gemm = [&](const float* Ain, const float* Win, const float* bias, float* C,
                    bool aff, int M, int Nn, int K, int relu) {
        dim3 gr(Nn / 128, (M + 127) / 128);
        k_gemm_bf16x3<<<gr, 256, GEMM_SMEM>>>(Ain, Win, bias, C,
                                              aff ? aA : nullptr, aff ? aD : nullptr,
                                              M, Nn, K, relu);
    };
    auto bn = [&](float* X, const float* bias, int wb, const float* gm,
                  const float* bt, int F) {
        dim3 gr((F + 31) / 32, BN_CHUNKS);
        k_bnpart<<<gr, 256>>>(X, bias, wb, NN, F, ps, pq);
        k_bnfin<<<(F + 127) / 128, 128>>>(ps, pq, gm, bt, aA, aD, F, BN_CHUNKS);
    };

    // Layer 1 (29 -> 1024): agg(x)->A; gemm(+b1,relu)->B=X1; stats->affine1
    agg(x, A, 29, false);
    gemm(A, W[0], b[0], B, false, NN, 1024, 29, 1);
    bn(B, nullptr, 0, g[0], be[0], 1024);

    // Layer 2 (1024->512): gemm(affine1 on A-load)->A; agg->B;
    //   bnpart writes back relu(B+b2) and stats -> affine2
    gemm(B, W[1], nullptr, A, true, NN, 512, 1024, 0);
    agg(A, B, 512, false);
    bn(B, b[1], 1, g[1], be[1], 512);

    // Layer 3 (512->256): gemm(affine2)->A; agg->B; writeback relu(B+b3)+stats
    gemm(B, W[2], nullptr, A, true, NN, 256, 512, 0);
    agg(A, B, 256, false);
    bn(B, b[2], 1, g[2], be[2], 256);

    // Layer 4 (256->512): agg(affine3 on loads)->A; gemm(+b4,relu)->B=X4
    agg(B, A, 256, true);
    gemm(A, W[3], b[3], B, false, NN, 512, 256, 1);
    bn(B, nullptr, 0, g[3], be[3], 512);

    // Layer 5 (512->1024): agg(affine4)->A; gemm(+b5,relu)->B=X5
    agg(B, A, 512, true);
    gemm(A, W[4], b[4], B, false, NN, 1024, 512, 1);
    bn(B, nullptr, 0, g[4], be[4], 1024);

    // ---- global attention pooling (affine5 applied on the fly) ----
    k_gate<<<(NN * 32 + 255) / 256, 256>>>(B, Wg, bg, aA, aD, gate);
    k_fill<<<(NG + 255) / 256, 256>>>(gmax, NG, -3e38f);
    k_fill<<<(NG + 255) / 256, 256>>>(gsum, NG, 0.0f);
    k_segmax<<<(NN + 255) / 256, 256>>>(gate, batch, gmax);
    k_exps<<<(NN + 255) / 256, 256>>>(gate, batch, gmax, gsum);
    k_coef<<<(NN + 255) / 256, 256>>>(gate, batch, gsum);
    k_fill<<<(NG * 1024 + 255) / 256, 256>>>(pool, (long)NG * 1024, 0.0f);
    k_pool4<<<(int)(((long)NN * 256 + 255) / 256), 256>>>(B, gate, batch, aA, aD, pool);

    // ---- MLP head ----
    k_mlp<<<(NG * 128 + 255) / 256, 256>>>(pool, Wf2, bf2, p2, NG, 128, 1024, 1);
    k_mlp<<<(NG * 16 + 255) / 256, 256>>>(p2, Wf3, bf3, p3, NG, 16, 128, 1);
    k_mlp<<<(NG + 255) / 256, 256>>>(p3, Wf4, bf4, (float*)d_out, NG, 1, 16, 0);
}

// round 16
// speedup vs baseline: 1.1626x; 1.1626x over previous
#include <cuda_runtime.h>
#include <cuda_bf16.h>
#include <cstdint>

#define NN 20000
#define NE 320000
#define NG 512
#define BN_CHUNKS 10

// ---------------- scratch (device globals; no allocation allowed) ----------
__device__ float g_bufA[NN * 1024];
__device__ float g_bufB[NN * 1024];
__device__ float g_deg[NN];
__device__ float g_dinv[NN];
__device__ float g_enorm[NE];
__device__ int   g_cnt[NN];
__device__ int   g_rowptr[NN + 1];
__device__ int   g_cursor[NN];
__device__ int   g_esrc[NE];
__device__ float g_ew[NE];
__device__ float g_mean[1024];
__device__ float g_rstd[1024];
__device__ float g_ps[BN_CHUNKS * 1024];
__device__ float g_pq[BN_CHUNKS * 1024];
__device__ int   g_gs[NG];
__device__ int   g_ge[NG];
__device__ float g_gate[NN];
__device__ float g_gmax[NG];
__device__ float g_gsum[NG];
__device__ float g_pool[NG * 1024];
__device__ float g_p2[NG * 128];
__device__ float g_p3[NG * 16];

// ---------------- small utility kernels ------------------------------------
__global__ void k_fill(float* p, long n, float v) {
    long i = (long)blockIdx.x * blockDim.x + threadIdx.x;
    if (i < n) p[i] = v;
}
__global__ void k_filli(int* p, int n, int v) {
    int i = blockIdx.x * blockDim.x + threadIdx.x;
    if (i < n) p[i] = v;
}

__global__ void k_deg(const int* __restrict__ col, float* __restrict__ deg) {
    int e = blockIdx.x * blockDim.x + threadIdx.x;
    if (e < NE) atomicAdd(&deg[col[e]], 1.0f);
}

__global__ void k_dinv(const float* __restrict__ deg, float* __restrict__ dinv,
                       int* __restrict__ cnt) {
    int i = blockIdx.x * blockDim.x + threadIdx.x;
    if (i < NN) {
        dinv[i] = rsqrtf(deg[i]);
        cnt[i] = (int)(deg[i] - 0.5f);   // in-degree (deg includes self +1)
    }
}

__global__ void k_enorm(const int* __restrict__ row, const int* __restrict__ col,
                        const float* __restrict__ dinv, float* __restrict__ nrm) {
    int e = blockIdx.x * blockDim.x + threadIdx.x;
    if (e < NE) nrm[e] = dinv[row[e]] * dinv[col[e]];
}

// single-block exclusive scan of cnt -> rowptr (chunked Hillis-Steele)
__global__ void k_scan(const int* __restrict__ cnt, int* __restrict__ rowptr) {
    __shared__ int s[1024];
    const int CH = 20;
    int t = threadIdx.x;
    int base = t * CH;
    int sum = 0;
    for (int i = 0; i < CH; i++) {
        int idx = base + i;
        if (idx < NN) sum += cnt[idx];
    }
    s[t] = sum;
    __syncthreads();
    for (int off = 1; off < 1024; off <<= 1) {
        int v = (t >= off) ? s[t - off] : 0;
        __syncthreads();
        s[t] += v;
        __syncthreads();
    }
    int excl = (t == 0) ? 0 : s[t - 1];
    int run = excl;
    for (int i = 0; i < CH; i++) {
        int idx = base + i;
        if (idx < NN) { rowptr[idx] = run; run += cnt[idx]; }
    }
    if (t == 1023) rowptr[NN] = s[1023];
}

__global__ void k_scatter(const int* __restrict__ row, const int* __restrict__ col,
                          const float* __restrict__ nrm, const int* __restrict__ rowptr,
                          int* __restrict__ cursor, int* __restrict__ esrc,
                          float* __restrict__ ew) {
    int e = blockIdx.x * blockDim.x + threadIdx.x;
    if (e >= NE) return;
    int c = col[e];
    int p = atomicAdd(&cursor[c], 1);
    int o = rowptr[c] + p;
    esrc[o] = row[e];
    ew[o] = nrm[e];
}

// per-graph node ranges (batch is sorted)
__global__ void k_bounds(const int* __restrict__ batch, int* __restrict__ gs,
                         int* __restrict__ ge) {
    int i = blockIdx.x * blockDim.x + threadIdx.x;
    if (i >= NN) return;
    int b = batch[i];
    atomicMin(&gs[b], i);
    atomicMax(&ge[b], i + 1);
}

// ---------------- CSR gather aggregation ------------------------------------
// dst[v] = dinv[v]^2 * src[v] + sum_{edges u->v} w_e * src[u]
// Warp per dst node; lane l owns float4 chunks at l*4 + c*128.
template <int NCH>   // F = NCH * 128
__global__ __launch_bounds__(256) void k_agg_gather(
    const float* __restrict__ src, float* __restrict__ dst,
    const int* __restrict__ rowptr, const int* __restrict__ esrc,
    const float* __restrict__ ew, const float* __restrict__ dinv)
{
    int gw = (blockIdx.x * blockDim.x + threadIdx.x) >> 5;
    if (gw >= NN) return;
    int lane = threadIdx.x & 31;
    const int F = NCH * 128;

    float4 acc[NCH];
    float dv = dinv[gw];
    float w0 = dv * dv;
    const float* srow = src + (long)gw * F + lane * 4;
#pragma unroll
    for (int c = 0; c < NCH; c++) {
        float4 t = *(const float4*)(srow + c * 128);
        acc[c] = make_float4(w0 * t.x, w0 * t.y, w0 * t.z, w0 * t.w);
    }

    int k0 = rowptr[gw], k1 = rowptr[gw + 1];
    for (int kb = k0; kb < k1; kb += 32) {
        int kk = kb + lane;
        int u_r = (kk < k1) ? esrc[kk] : 0;
        float w_r = (kk < k1) ? ew[kk] : 0.0f;
        int cnt = min(32, k1 - kb);
        for (int j = 0; j < cnt; j++) {
            int u = __shfl_sync(0xffffffffu, u_r, j);
            float w = __shfl_sync(0xffffffffu, w_r, j);
            const float* r = src + (long)u * F + lane * 4;
#pragma unroll
            for (int c = 0; c < NCH; c++) {
                float4 t = *(const float4*)(r + c * 128);
                acc[c].x += w * t.x; acc[c].y += w * t.y;
                acc[c].z += w * t.z; acc[c].w += w * t.w;
            }
        }
    }

    float* drow = dst + (long)gw * F + lane * 4;
#pragma unroll
    for (int c = 0; c < NCH; c++)
        *(float4*)(drow + c * 128) = acc[c];
}

// small-F (F <= 32) gather: lane per feature
__global__ __launch_bounds__(256) void k_agg_gather_s(
    const float* __restrict__ src, float* __restrict__ dst,
    const int* __restrict__ rowptr, const int* __restrict__ esrc,
    const float* __restrict__ ew, const float* __restrict__ dinv, int F)
{
    int gw = (blockIdx.x * blockDim.x + threadIdx.x) >> 5;
    if (gw >= NN) return;
    int lane = threadIdx.x & 31;
    float acc = 0.0f;
    float dv = dinv[gw];
    float w0 = dv * dv;
    if (lane < F) acc = w0 * src[(long)gw * F + lane];
    int k0 = rowptr[gw], k1 = rowptr[gw + 1];
    for (int kb = k0; kb < k1; kb += 32) {
        int kk = kb + lane;
        int u_r = (kk < k1) ? esrc[kk] : 0;
        float w_r = (kk < k1) ? ew[kk] : 0.0f;
        int cnt = min(32, k1 - kb);
        for (int j = 0; j < cnt; j++) {
            int u = __shfl_sync(0xffffffffu, u_r, j);
            float w = __shfl_sync(0xffffffffu, w_r, j);
            if (lane < F) acc += w * src[(long)u * F + lane];
        }
    }
    if (lane < F) dst[(long)gw * F + lane] = acc;
}

// ---------------- 3x-BF16 tensor-core GEMM ---------------------------------
// C[M,N] = A[M,K] @ W[K,N] (+bias, relu). N multiple of 128. Block 128x128,
// 8 warps of 64x32, mma.sync m16n8k16 bf16 with hi/lo error compensation
// (acc += ah*bh + ah*bl + al*bh). BK=32 double-buffered; hi/lo packed as
// bf16x2 k-pairs (uint2) once at stage time; mainloop = LDS.64 + MMA only.
__device__ __forceinline__ uint2 bf16split2(float f0, float f1) {
    __nv_bfloat162 h = __floats2bfloat162_rn(f0, f1);     // .x = f0 (low k)
    float h0 = __bfloat162float(__low2bfloat16(h));
    float h1 = __bfloat162float(__high2bfloat16(h));
    __nv_bfloat162 l = __floats2bfloat162_rn(f0 - h0, f1 - h1);
    uint2 r;
    r.x = *reinterpret_cast<uint32_t*>(&h);
    r.y = *reinterpret_cast<uint32_t*>(&l);
    return r;
}

__device__ __forceinline__ void mma_bf16(float* d, const uint32_t* a, const uint32_t* b) {
    asm volatile(
        "mma.sync.aligned.m16n8k16.row.col.f32.bf16.bf16.f32 "
        "{%0,%1,%2,%3}, {%4,%5,%6,%7}, {%8,%9}, {%0,%1,%2,%3};"
        : "+f"(d[0]), "+f"(d[1]), "+f"(d[2]), "+f"(d[3])
        : "r"(a[0]), "r"(a[1]), "r"(a[2]), "r"(a[3]), "r"(b[0]), "r"(b[1]));
}

#define KP 16      // k-pairs per BK=32 tile
#define LDP 132    // padded row length (uint2 elements)

__global__ __launch_bounds__(256) void k_gemm_bf16x3(
    const float* __restrict__ A, const float* __restrict__ W,
    const float* __restrict__ bias, float* __restrict__ C,
    int M, int N, int K, int doRelu)
{
    extern __shared__ uint2 smem[];
    uint2* Asm = smem;                    // [2][KP][LDP]  (hi,lo) of A k-pairs
    uint2* Bsm = smem + 2 * KP * LDP;     // [2][KP][LDP]  (hi,lo) of W k-pairs
#define AS(b, kp, m) Asm[((b) * KP + (kp)) * LDP + (m)]
#define BS(b, kp, n) Bsm[((b) * KP + (kp)) * LDP + (n)]

    const int tid = threadIdx.x;
    const int lane = tid & 31;
    const int warp = tid >> 5;
    const int wm = warp >> 2, wn = warp & 3;
    const int gr = lane >> 2, gk = lane & 3;
    const int bm = blockIdx.y * 128, bn = blockIdx.x * 128;

    float acc[4][4][4];
#pragma unroll
    for (int i = 0; i < 4; i++)
#pragma unroll
        for (int j = 0; j < 4; j++)
#pragma unroll
            for (int r = 0; r < 4; r++) acc[i][j][r] = 0.0f;

    const int nc = (K + 31) / 32;
    const bool vec = (K & 31) == 0;

    const int ar = tid >> 1, akb = (tid & 1) * 16;  // A: row, k base (16 wide)
    const int wr2 = tid >> 5, wc = (tid & 31) * 4;  // B: k-pair row, col base

    float ra[16];
    float rb[16];

    auto fetch = [&](int c) {
        int k0 = c * 32;
        int g = bm + ar;
        if (vec) {
            if (g < M) {
                const float* p = A + (long)g * K + k0 + akb;
#pragma unroll
                for (int h = 0; h < 4; h++) {
                    float4 v = *(const float4*)(p + h * 4);
                    ra[h * 4 + 0] = v.x; ra[h * 4 + 1] = v.y;
                    ra[h * 4 + 2] = v.z; ra[h * 4 + 3] = v.w;
                }
            } else {
#pragma unroll
                for (int q = 0; q < 16; q++) ra[q] = 0.0f;
            }
        } else {
#pragma unroll
            for (int q = 0; q < 16; q++) {
                int kk = k0 + akb + q;
                ra[q] = (g < M && kk < K) ? A[(long)g * K + kk] : 0.0f;
            }
        }
        // B rows: k-pair wr2 -> rows k0+2*wr2, +1 ; k-pair wr2+8 -> +16, +17
        int r0 = k0 + 2 * wr2;
#pragma unroll
        for (int h = 0; h < 4; h++) {
            int kk = r0 + (h >> 1) * 16 + (h & 1);
            if (kk < K) {
                float4 v = *(const float4*)(W + (long)kk * N + bn + wc);
                rb[h * 4 + 0] = v.x; rb[h * 4 + 1] = v.y;
                rb[h * 4 + 2] = v.z; rb[h * 4 + 3] = v.w;
            } else {
                rb[h * 4 + 0] = rb[h * 4 + 1] = rb[h * 4 + 2] = rb[h * 4 + 3] = 0.0f;
            }
        }
    };
    auto stage = [&](int buf) {
#pragma unroll
        for (int q = 0; q < 8; q++)
            AS(buf, (tid & 1) * 8 + q, ar) = bf16split2(ra[2 * q], ra[2 * q + 1]);
#pragma unroll
        for (int c4 = 0; c4 < 4; c4++) {
            BS(buf, wr2, wc + c4)     = bf16split2(rb[c4],     rb[4 + c4]);
            BS(buf, wr2 + 8, wc + c4) = bf16split2(rb[8 + c4], rb[12 + c4]);
        }
    };

    fetch(0);
    stage(0);
    __syncthreads();

    for (int c = 0; c < nc; c++) {
        int buf = c & 1;
        if (c + 1 < nc) fetch(c + 1);   // LDGs overlap compute below
#pragma unroll
        for (int kk = 0; kk < 2; kk++) {
            int kb = kk * 8;
            uint32_t ah[4][4], al[4][4], bh[4][2], bl[4][2];
#pragma unroll
            for (int i = 0; i < 4; i++) {
                int m = wm * 64 + i * 16 + gr;
                uint2 v0 = AS(buf, kb + gk, m);
                uint2 v1 = AS(buf, kb + gk, m + 8);
                uint2 v2 = AS(buf, kb + gk + 4, m);
                uint2 v3 = AS(buf, kb + gk + 4, m + 8);
                ah[i][0] = v0.x; al[i][0] = v0.y;
                ah[i][1] = v1.x; al[i][1] = v1.y;
                ah[i][2] = v2.x; al[i][2] = v2.y;
                ah[i][3] = v3.x; al[i][3] = v3.y;
            }
#pragma unroll
            for (int j = 0; j < 4; j++) {
                int n = wn * 32 + j * 8 + gr;
                uint2 u0 = BS(buf, kb + gk, n);
                uint2 u1 = BS(buf, kb + gk + 4, n);
                bh[j][0] = u0.x; bl[j][0] = u0.y;
                bh[j][1] = u1.x; bl[j][1] = u1.y;
            }
#pragma unroll
            for (int i = 0; i < 4; i++)
#pragma unroll
                for (int j = 0; j < 4; j++) {
                    mma_bf16(acc[i][j], al[i], bh[j]);   // lo*hi
                    mma_bf16(acc[i][j], ah[i], bl[j]);   // hi*lo
                    mma_bf16(acc[i][j], ah[i], bh[j]);   // hi*hi
                }
        }
        if (c + 1 < nc) {
            stage((c + 1) & 1);   // writes buf^1: protected by previous sync
        }
        __syncthreads();
    }

    // epilogue
#pragma unroll
    for (int i = 0; i < 4; i++) {
        int r0 = bm + wm * 64 + i * 16 + gr;
        int r1 = r0 + 8;
#pragma unroll
        for (int j = 0; j < 4; j++) {
            int cc = bn + wn * 32 + j * 8 + gk * 2;
            float b0 = bias ? bias[cc] : 0.0f;
            float b1 = bias ? bias[cc + 1] : 0.0f;
            float v0 = acc[i][j][0] + b0, v1 = acc[i][j][1] + b1;
            float v2 = acc[i][j][2] + b0, v3 = acc[i][j][3] + b1;
            if (doRelu) {
                v0 = fmaxf(v0, 0.0f); v1 = fmaxf(v1, 0.0f);
                v2 = fmaxf(v2, 0.0f); v3 = fmaxf(v3, 0.0f);
            }
            if (r0 < M) *(float2*)(C + (long)r0 * N + cc) = make_float2(v0, v1);
            if (r1 < M) *(float2*)(C + (long)r1 * N + cc) = make_float2(v2, v3);
        }
    }
#undef AS
#undef BS
}

#define GEMM_SMEM (2 * 2 * KP * LDP * (int)sizeof(uint2))

// ---------------- BatchNorm (training-mode, biased var), two pass ----------
__global__ void k_bnpart(const float* __restrict__ X, const float* __restrict__ bias,
                         int M, int N, float* __restrict__ ps, float* __restrict__ pq) {
    int lane = threadIdx.x & 31, ry = threadIdx.x >> 5;  // block 256 = 8x32
    int c = blockIdx.x * 32 + lane;
    int nch = gridDim.y;
    int per = (M + nch - 1) / nch;
    int r0 = blockIdx.y * per;
    int r1 = min(M, r0 + per);
    float s = 0.0f, q = 0.0f;
    if (c < N) {
        float bb = bias ? bias[c] : 0.0f;
        bool rl = (bias != nullptr);
        for (int r = r0 + ry; r < r1; r += 8) {
            float v = X[(long)r * N + c];
            if (rl) v = fmaxf(v + bb, 0.0f);
            s += v;
            q += v * v;
        }
    }
    __shared__ float sh[16][32];
    sh[ry][lane] = s;
    sh[8 + ry][lane] = q;
    __syncthreads();
    if (ry == 0 && c < N) {
#pragma unroll
        for (int i = 1; i < 8; i++) { s += sh[i][lane]; q += sh[8 + i][lane]; }
        ps[blockIdx.y * N + c] = s;
        pq[blockIdx.y * N + c] = q;
    }
}

__global__ void k_bnfin(const float* __restrict__ ps, const float* __restrict__ pq,
                        int N, int nch, float* __restrict__ mean, float* __restrict__ rstd) {
    int c = blockIdx.x * blockDim.x + threadIdx.x;
    if (c >= N) return;
    float s = 0.0f, q = 0.0f;
    for (int i = 0; i < nch; i++) { s += ps[i * N + c]; q += pq[i * N + c]; }
    float m = s / (float)NN;
    mean[c] = m;
    float var = q / (float)NN - m * m;
    rstd[c] = rsqrtf(fmaxf(var, 0.0f) + 1e-5f);
}

// float4 BN apply; N is a power of two (mask = N-1), 4 consecutive features
// never wrap since N % 4 == 0.
__global__ void k_bnapply4(float* __restrict__ X, const float* __restrict__ bias,
                           const float* __restrict__ gm, const float* __restrict__ bt,
                           const float* __restrict__ mean, const float* __restrict__ rstd,
                           long tot4, int mask) {
    long i = (long)blockIdx.x * blockDim.x + threadIdx.x;
    if (i >= tot4) return;
    int c = (int)((i * 4) & mask);
    float4 v = ((float4*)X)[i];
    if (bias) {
        float4 bb = *(const float4*)(bias + c);
        v.x = fmaxf(v.x + bb.x, 0.0f); v.y = fmaxf(v.y + bb.y, 0.0f);
        v.z = fmaxf(v.z + bb.z, 0.0f); v.w = fmaxf(v.w + bb.w, 0.0f);
    }
    float4 gm4 = *(const float4*)(gm + c);
    float4 bt4 = *(const float4*)(bt + c);
    float4 m4  = *(const float4*)(mean + c);
    float4 r4  = *(const float4*)(rstd + c);
    v.x = fmaf(gm4.x * r4.x, v.x - m4.x, bt4.x);
    v.y = fmaf(gm4.y * r4.y, v.y - m4.y, bt4.y);
    v.z = fmaf(gm4.z * r4.z, v.z - m4.z, bt4.z);
    v.w = fmaf(gm4.w * r4.w, v.w - m4.w, bt4.w);
    ((float4*)X)[i] = v;
}

// ---------------- global attention pooling ---------------------------------
__global__ void k_gate(const float* __restrict__ H, const float* __restrict__ Wg,
                       const float* __restrict__ bg, float* __restrict__ gate) {
    int t = blockIdx.x * blockDim.x + threadIdx.x;
    int v = t >> 5, lane = t & 31;
    if (v >= NN) return;
    const float* h = H + (long)v * 1024;
    float s = 0.0f;
    for (int k = lane; k < 1024; k += 32) s += h[k] * Wg[k];
#pragma unroll
    for (int o = 16; o; o >>= 1) s += __shfl_down_sync(0xffffffffu, s, o);
    if (lane == 0) gate[v] = s + bg[0];
}

__global__ void k_segmax(const float* __restrict__ gate, const int* __restrict__ batch,
                         float* __restrict__ gmax) {
    int i = blockIdx.x * blockDim.x + threadIdx.x;
    if (i >= NN) return;
    float v = gate[i];
    float* addr = &gmax[batch[i]];
    int old = __float_as_int(*addr);
    while (v > __int_as_float(old)) {
        int prev = atomicCAS((int*)addr, old, __float_as_int(v));
        if (prev == old) break;
        old = prev;
    }
}

__global__ void k_exps(float* __restrict__ gate, const int* __restrict__ batch,
                       const float* __restrict__ gmax, float* __restrict__ gsum) {
    int i = blockIdx.x * blockDim.x + threadIdx.x;
    if (i >= NN) return;
    int b = batch[i];
    float e = expf(gate[i] - gmax[b]);
    gate[i] = e;
    atomicAdd(&gsum[b], e);
}

__global__ void k_coef(float* __restrict__ gate, const int* __restrict__ batch,
                       const float* __restrict__ gsum) {
    int i = blockIdx.x * blockDim.x + threadIdx.x;
    if (i >= NN) return;
    gate[i] = gate[i] / gsum[batch[i]];
}

// segment pooling: block = (graph, 256-feature chunk); no atomics.
__global__ void k_poolseg(const float* __restrict__ H, const float* __restrict__ gate,
                          const int* __restrict__ gs, const int* __restrict__ ge,
                          float* __restrict__ pool) {
    int g = blockIdx.x;
    int f = blockIdx.y * 256 + threadIdx.x;
    float acc = 0.0f;
    int s = gs[g], e = ge[g];
    for (int r = s; r < e; r++)
        acc += gate[r] * H[((long)r << 10) + f];
    pool[((long)g << 10) + f] = acc;
}

// ---------------- small MLP GEMMs ------------------------------------------
__global__ void k_mlp(const float* __restrict__ X, const float* __restrict__ W,
                      const float* __restrict__ bias, float* __restrict__ Y,
                      int M, int N, int K, int relu) {
    int i = blockIdx.x * blockDim.x + threadIdx.x;
    if (i >= M * N) return;
    int m = i / N, n = i % N;
    float s = bias[n];
    for (int k = 0; k < K; k++) s += X[m * K + k] * W[k * N + n];
    if (relu) s = fmaxf(s, 0.0f);
    Y[i] = s;
}

// ---------------- launch -----------------------------------------------------
extern "C" void kernel_launch(void* const* d_in, const int* in_sizes, int n_in,
                              void* d_out, int out_size) {
    (void)in_sizes; (void)n_in; (void)out_size;
    const float* x = (const float*)d_in[0];
    const int* ei = (const int*)d_in[1];
    const int* row = ei;
    const int* col = ei + NE;
    const int* batch = (const int*)d_in[2];
    const float *W[5], *b[5], *g[5], *be[5];
    for (int i = 0; i < 5; i++) {
        W[i]  = (const float*)d_in[3 + 4 * i];
        b[i]  = (const float*)d_in[4 + 4 * i];
        g[i]  = (const float*)d_in[5 + 4 * i];
        be[i] = (const float*)d_in[6 + 4 * i];
    }
    const float* Wg  = (const float*)d_in[23];
    const float* bg  = (const float*)d_in[24];
    const float* Wf2 = (const float*)d_in[25];
    const float* bf2 = (const float*)d_in[26];
    const float* Wf3 = (const float*)d_in[27];
    const float* bf3 = (const float*)d_in[28];
    const float* Wf4 = (const float*)d_in[29];
    const float* bf4 = (const float*)d_in[30];

    static int s_attr_done = 0;
    if (!s_attr_done) {
        cudaFuncSetAttribute(k_gemm_bf16x3,
                             cudaFuncAttributeMaxDynamicSharedMemorySize, GEMM_SMEM);
        s_attr_done = 1;
    }

    float *A, *B, *deg, *dinv, *nrm, *mean, *rstd, *ps, *pq, *ew;
    float *gate, *gmax, *gsum, *pool, *p2, *p3;
    int *cnt, *rowptr, *cursor, *esrc, *gs, *ge;
    cudaGetSymbolAddress((void**)&A, g_bufA);
    cudaGetSymbolAddress((void**)&B, g_bufB);
    cudaGetSymbolAddress((void**)&deg, g_deg);
    cudaGetSymbolAddress((void**)&dinv, g_dinv);
    cudaGetSymbolAddress((void**)&nrm, g_enorm);
    cudaGetSymbolAddress((void**)&cnt, g_cnt);
    cudaGetSymbolAddress((void**)&rowptr, g_rowptr);
    cudaGetSymbolAddress((void**)&cursor, g_cursor);
    cudaGetSymbolAddress((void**)&esrc, g_esrc);
    cudaGetSymbolAddress((void**)&ew, g_ew);
    cudaGetSymbolAddress((void**)&mean, g_mean);
    cudaGetSymbolAddress((void**)&rstd, g_rstd);
    cudaGetSymbolAddress((void**)&ps, g_ps);
    cudaGetSymbolAddress((void**)&pq, g_pq);
    cudaGetSymbolAddress((void**)&gs, g_gs);
    cudaGetSymbolAddress((void**)&ge, g_ge);
    cudaGetSymbolAddress((void**)&gate, g_gate);
    cudaGetSymbolAddress((void**)&gmax, g_gmax);
    cudaGetSymbolAddress((void**)&gsum, g_gsum);
    cudaGetSymbolAddress((void**)&pool, g_pool);
    cudaGetSymbolAddress((void**)&p2, g_p2);
    cudaGetSymbolAddress((void**)&p3, g_p3);

    // ---- graph normalization + CSR build (depends only on edge_index) ----
    k_fill<<<(NN + 255) / 256, 256>>>(deg, NN, 1.0f);            // self-loop
    k_deg<<<(NE + 255) / 256, 256>>>(col, deg);
    k_dinv<<<(NN + 255) / 256, 256>>>(deg, dinv, cnt);
    k_enorm<<<(NE + 255) / 256, 256>>>(row, col, dinv, nrm);
    k_scan<<<1, 1024>>>(cnt, rowptr);
    k_filli<<<(NN + 255) / 256, 256>>>(cursor, NN, 0);
    k_scatter<<<(NE + 255) / 256, 256>>>(row, col, nrm, rowptr, cursor, esrc, ew);
    k_filli<<<(NG + 255) / 256, 256>>>(gs, NG, NN);
    k_filli<<<(NG + 255) / 256, 256>>>(ge, NG, 0);
    k_bounds<<<(NN + 255) / 256, 256>>>(batch, gs, ge);

    const int AGG_GRID = (NN * 32 + 255) / 256;
    auto agg = [&](const float* src, float* dst, int F) {
        if (F == 512)
            k_agg_gather<4><<<AGG_GRID, 256>>>(src, dst, rowptr, esrc, ew, dinv);
        else if (F == 256)
            k_agg_gather<2><<<AGG_GRID, 256>>>(src, dst, rowptr, esrc, ew, dinv);
        else
            k_agg_gather_s<<<AGG_GRID, 256>>>(src, dst, rowptr, esrc, ew, dinv, F);
    };
    auto gemm = [&](const float* Ain, const float* Win, const float* bias, float* C,
                    int M, int Nn, int K, int relu) {
        dim3 gr(Nn / 128, (M + 127) / 128);
        k_gemm_bf16x3<<<gr, 256, GEMM_SMEM>>>(Ain, Win, bias, C, M, Nn, K, relu);
    };
    auto bn = [&](float* X, const float* bias, const float* gm, const float* bt, int F) {
        dim3 gr((F + 31) / 32, BN_CHUNKS);
        k_bnpart<<<gr, 256>>>(X, bias, NN, F, ps, pq);
        k_bnfin<<<(F + 127) / 128, 128>>>(ps, pq, F, BN_CHUNKS, mean, rstd);
        long tot4 = (long)NN * F / 4;
        k_bnapply4<<<(int)((tot4 + 255) / 256), 256>>>(X, bias, gm, bt, mean, rstd,
                                                       tot4, F - 1);
    };

    // Layer 1 (29 -> 1024): aggregate first (29 feats), then GEMM(+b,relu), BN
    agg(x, A, 29);
    gemm(A, W[0], b[0], B, NN, 1024, 29, 1);
    bn(B, nullptr, g[0], be[0], 1024);

    // Layer 2 (1024 -> 512): GEMM first, aggregate on 512, then b+relu+BN fused
    gemm(B, W[1], nullptr, A, NN, 512, 1024, 0);
    agg(A, B, 512);
    bn(B, b[1], g[1], be[1], 512);

    // Layer 3 (512 -> 256): GEMM first, aggregate on 256
    gemm(B, W[2], nullptr, A, NN, 256, 512, 0);
    agg(A, B, 256);
    bn(B, b[2], g[2], be[2], 256);

    // Layer 4 (256 -> 512): aggregate first (256), GEMM(+b,relu), BN
    agg(B, A, 256);
    gemm(A, W[3], b[3], B, NN, 512, 256, 1);
    bn(B, nullptr, g[3], be[3], 512);

    // Layer 5 (512 -> 1024): aggregate first (512), GEMM(+b,relu), BN
    agg(B, A, 512);
    gemm(A, W[4], b[4], B, NN, 1024, 512, 1);
    bn(B, nullptr, g[4], be[4], 1024);

    // ---- global attention pooling (segment reduction; batch is sorted) ----
    k_gate<<<(NN * 32 + 255) / 256, 256>>>(B, Wg, bg, gate);
    k_fill<<<(NG + 255) / 256, 256>>>(gmax, NG, -3e38f);
    k_fill<<<(NG + 255) / 256, 256>>>(gsum, NG, 0.0f);
    k_segmax<<<(NN + 255) / 256, 256>>>(gate, batch, gmax);
    k_exps<<<(NN + 255) / 256, 256>>>(gate, batch, gmax, gsum);
    k_coef<<<(NN + 255) / 256, 256>>>(gate, batch, gsum);
    {
        dim3 gp(NG, 4);
        k_poolseg<<<gp, 256>>>(B, gate, gs, ge, pool);
    }

    // ---- MLP head ----
    k_mlp<<<(NG * 128 + 255) / 256, 256>>>(pool, Wf2, bf2, p2, NG, 128, 1024, 1);
    k_mlp<<<(NG * 16 + 255) / 256, 256>>>(p2, Wf3, bf3, p3, NG, 16, 128, 1);
    k_mlp<<<(NG + 255) / 256, 256>>>(p3, Wf4, bf4, (float*)d_out, NG, 1, 16, 0);
}